// round 16
// baseline (speedup 1.0000x reference)
#include <cuda_runtime.h>
#include <cuda_bf16.h>

#define FEAT_C 512
#define FEAT_H 100
#define FEAT_W 152
#define NUM_ROIS 512
#define AH 14
#define AW 14
#define SPATIAL_SCALE 0.0625f
#define CH_CHUNK 32
#define CHUNKS_PER_ROI (FEAT_C / CH_CHUNK)   // 16
#define BINS (AH * AW)                       // 196
#define HW (FEAT_H * FEAT_W)

// Separable RoI-align, v9 = v8 (71.0us) with CH_CHUNK 16->32 at the PROVEN
// (224,6) reg config.  (R8's CH=32 failure was confounded by minblocks=7,
// which R9 showed collapses regs to 32 on its own; CH=32 @ minblocks=6 was
// never tested.)  Halves per-work setup overhead (~30% of issued instrs) and
// block count.
//  - warp = one ph-pair; chunk-major (512 consecutive blocks share a 3.8MB
//    channel slice -> L2-resident reads, writes-only DRAM).
//  - FAST PATH (nx<=16): la lanes 0-15 / lb lanes 16-31, one shuffle per
//    bilinear source, 2 channels/iter (MLP=4).
//  - SLOW PATH (nx>16): R7 body (4 shuffles, reuse branch kept).
__global__ __launch_bounds__(224, 6) void roi_align_kernel(
    const float* __restrict__ feat,
    const float* __restrict__ rois,
    float* __restrict__ out)
{
    const int r     = blockIdx.x & (NUM_ROIS - 1);      // % 512
    const int chunk = blockIdx.x >> 9;                  // / 512
    const int c0    = chunk * CH_CHUNK;

    const int tid  = threadIdx.x;
    const int wid  = tid >> 5;                          // 0..6 -> ph pair
    const int lane = tid & 31;

    // ---- roi params ----
    const float* rp = rois + r * 5;
    const int   b       = (int)rp[0];
    const float x_start = rp[1] * SPATIAL_SCALE;
    const float y_start = rp[2] * SPATIAL_SCALE;
    const float x_end   = rp[3] * SPATIAL_SCALE;
    const float y_end   = rp[4] * SPATIAL_SCALE;

    const float roi_w = fmaxf(x_end - x_start, 0.0f);
    const float roi_h = fmaxf(y_end - y_start, 0.0f);
    const float bin_h = roi_h * (1.0f / (float)(AH - 1));
    const float bin_w = roi_w * (1.0f / (float)(AW - 1));

    // ---- x footprint (uniform across block): span <= 29 floats ----
    const float xs0c = fminf(fmaxf(x_start, 0.0f), (float)(FEAT_W - 1));
    const float xsEc = fminf(fmaxf(x_end,   0.0f), (float)(FEAT_W - 1));
    const int x_lo = (int)floorf(xs0c);
    const int x_hi = min((int)floorf(xsEc) + 1, FEAT_W - 1);
    const int nx   = x_hi - x_lo + 1;

    // ---- per-lane x interp params ----
    const int pw = (lane < 16) ? min(lane, AW - 1) : min(lane - 16, AW - 1);
    float xs = x_start + (float)pw * bin_w;
    xs = fminf(fmaxf(xs, 0.0f), (float)(FEAT_W - 1));
    const int   x0  = (int)floorf(xs);
    const int   x1  = min(x0 + 1, FEAT_W - 1);
    const float wx  = xs - (float)x0;
    const int   sx0 = x0 - x_lo;                        // in [0, nx-1]
    const int   sx1 = x1 - x_lo;                        // in [0, nx-1]

    // ---- per-warp y params ----
    const int ph_a = wid * 2;
    float ysa = y_start + (float)ph_a * bin_h;
    float ysb = y_start + (float)(ph_a + 1) * bin_h;
    ysa = fminf(fmaxf(ysa, 0.0f), (float)(FEAT_H - 1));
    ysb = fminf(fmaxf(ysb, 0.0f), (float)(FEAT_H - 1));
    const int   ya0 = (int)floorf(ysa);
    const int   ya1 = min(ya0 + 1, FEAT_H - 1);
    const float wya = ysa - (float)ya0;
    const int   yb0 = (int)floorf(ysb);
    const int   yb1 = min(yb0 + 1, FEAT_H - 1);
    const float wyb = ysb - (float)yb0;
    const bool  reuse = (yb0 == ya1);

    const float* fbase = feat + ((size_t)b * FEAT_C + c0) * HW + x_lo;
    const int oa0 = ya0 * FEAT_W, oa1 = ya1 * FEAT_W;
    const int ob0 = yb0 * FEAT_W, ob1 = yb1 * FEAT_W;

    float* op = out + ((size_t)r * FEAT_C + c0) * BINS + ph_a * AW;
    const bool stok = (lane < 14) || (lane >= 16 && lane < 30);
    const int  soff = (lane < 14) ? lane : (lane - 2);

    if (nx <= 16) {
        // ======== FAST PATH: 2 channels/iter, 4 LDG + 4 SHFL + 2 STG =======
        const int  col     = lane & 15;
        const int  col_off = min(col, nx - 1);
        const bool hi      = (lane >= 16);
        const int  ro0     = hi ? ob0 : oa0;
        const int  ro1     = hi ? ob1 : oa1;
        const float wyl    = hi ? wyb : wya;
        const float* base  = fbase + col_off;
        const int  src0    = (lane & 16) | sx0;         // own half-warp
        const int  src1    = (lane & 16) | sx1;

        #pragma unroll
        for (int cc = 0; cc < CH_CHUNK; cc += 2) {
            const float* fA = base + cc * HW;
            const float* fB = fA + HW;

            const float Ar0 = __ldg(fA + ro0);
            const float Ar1 = __ldg(fA + ro1);
            const float Br0 = __ldg(fB + ro0);
            const float Br1 = __ldg(fB + ro1);

            const float Am = fmaf(wyl, Ar1 - Ar0, Ar0);
            const float Bm = fmaf(wyl, Br1 - Br0, Br0);

            const float As0 = __shfl_sync(0xffffffffu, Am, src0);
            const float As1 = __shfl_sync(0xffffffffu, Am, src1);
            const float Bs0 = __shfl_sync(0xffffffffu, Bm, src0);
            const float Bs1 = __shfl_sync(0xffffffffu, Bm, src1);

            const float Av = fmaf(wx, As1 - As0, As0);
            const float Bv = fmaf(wx, Bs1 - Bs0, Bs0);

            if (stok) {
                op[cc * BINS + soff]       = Av;
                op[(cc + 1) * BINS + soff] = Bv;
            }
        }
    } else {
        // ================= SLOW PATH: R7 body (span in all lanes) ==========
        const bool ldok = (lane < nx);
        const float* base = fbase;

        #pragma unroll
        for (int cc = 0; cc < CH_CHUNK; cc++) {
            const float* f = base + cc * HW;
            float ra0 = ldok ? __ldg(f + oa0 + lane) : 0.0f;
            float ra1 = ldok ? __ldg(f + oa1 + lane) : 0.0f;
            float rb1 = ldok ? __ldg(f + ob1 + lane) : 0.0f;
            float rb0;
            if (reuse) {
                rb0 = ra1;
            } else {
                rb0 = ldok ? __ldg(f + ob0 + lane) : 0.0f;
            }

            const float la = fmaf(wya, ra1 - ra0, ra0);
            const float lb = fmaf(wyb, rb1 - rb0, rb0);

            const float a0 = __shfl_sync(0xffffffffu, la, sx0);
            const float a1 = __shfl_sync(0xffffffffu, la, sx1);
            const float b0 = __shfl_sync(0xffffffffu, lb, sx0);
            const float b1 = __shfl_sync(0xffffffffu, lb, sx1);

            const float s0 = (lane < 16) ? a0 : b0;
            const float s1 = (lane < 16) ? a1 : b1;
            const float v  = fmaf(wx, s1 - s0, s0);

            if (stok) op[cc * BINS + soff] = v;
        }
    }
}

extern "C" void kernel_launch(void* const* d_in, const int* in_sizes, int n_in,
                              void* d_out, int out_size)
{
    const float* feat = (const float*)d_in[0];
    const float* rois = (const float*)d_in[1];
    float* out = (float*)d_out;

    dim3 grid(NUM_ROIS * CHUNKS_PER_ROI);   // 8192, chunk-major
    dim3 block(224);
    roi_align_kernel<<<grid, block>>>(feat, rois, out);
}